// round 15
// baseline (speedup 1.0000x reference)
#include <cuda_runtime.h>
#include <cuda_fp16.h>
#include <math.h>
#include <stdint.h>

#define NT 16384
#define NE 16384
#define BETA 0.25f

#define RH  88                      // halves per padded row (80 data, 8 pad)
#define RBH 176                     // bytes per row (11*16 -> conflict-free ldmatrix)
#define TILEH (128 * RBH)           // B subtile bytes = 22528
#define CHUNKH (TILEH / 16)         // 1408
#define ATILE (256 * RBH)           // A tile bytes = 45056
#define CHUNKA (ATILE / 16)         // 2816

#define MK1 4.0e-4f                 // q-domain margin slope * sqrt(zn)
#define MK2 7.0e-3f                 // q-domain margin offset (validated R13/R14)

// ---------------- static device scratch ----------------
__device__ __half g_zh[16384 * RH];   // [zh | 1 | 0...] padded rows
__device__ __half g_eh[16384 * RH];   // [Eh | -2048*en | 0...] (E = 4096*e)
__device__ float g_enorm[NE];
__device__ float g_znorm[NT];
__device__ float g_gmax[(size_t)NT * 256];  // per-token, per-64-code-group acc max
__device__ int   g_idx[NT];
__device__ int   g_counts[NE];
__device__ float g_loss;
__device__ float g_ent;
__device__ int   g_cu;
__device__ int   g_tick;

// ---------------- helpers ----------------
__device__ __forceinline__ uint32_t smem_u32(const void* p) {
    uint32_t a;
    asm("{ .reg .u64 t; cvta.to.shared.u64 t, %1; cvt.u32.u64 %0, t; }" : "=r"(a) : "l"(p));
    return a;
}
__device__ __forceinline__ __half2 u2h(uint32_t u) {
    return *reinterpret_cast<__half2*>(&u);
}

#define CP_ASYNC16(dst_u32, src_ptr) \
    asm volatile("cp.async.cg.shared.global [%0], [%1], 16;\n" :: "r"(dst_u32), "l"(src_ptr))
#define CP_COMMIT()  asm volatile("cp.async.commit_group;\n" ::: "memory")
#define CP_WAIT0()   asm volatile("cp.async.wait_group 0;\n" ::: "memory")

#define LDSM_X4(r, addr) \
    asm volatile("ldmatrix.sync.aligned.m8n8.x4.shared.b16 {%0,%1,%2,%3}, [%4];" \
        : "=r"((r)[0]), "=r"((r)[1]), "=r"((r)[2]), "=r"((r)[3]) : "r"(addr))

// fp16-accumulate mma
__device__ __forceinline__ void mma16816h(uint32_t* c, const uint32_t* a, const uint32_t* b) {
    asm volatile(
        "mma.sync.aligned.m16n8k16.row.col.f16.f16.f16.f16 "
        "{%0,%1}, {%2,%3,%4,%5}, {%6,%7}, {%0,%1};"
        : "+r"(c[0]), "+r"(c[1])
        : "r"(a[0]), "r"(a[1]), "r"(a[2]), "r"(a[3]), "r"(b[0]), "r"(b[1]));
}

// ---------------- prep: h tiles with folded norm column; zero state ----------------
__global__ void k_split(const float* __restrict__ z, const float* __restrict__ emb) {
    extern __shared__ __half st[];          // 128*RH halves = 22528 B
    int blk = blockIdx.x;                   // 0..127 z tiles, 128..255 e subtiles
    int tid = threadIdx.x;                  // 256
    if (blk < 128) {
        int tile = blk;
        int b = tile >> 3, hw0 = (tile & 7) << 7;
        for (int idx = tid; idx < 8192; idx += 256) {
            int k = idx >> 7, tl = idx & 127;
            float v = z[((size_t)(b * 64 + k) << 10) + hw0 + tl];
            st[tl * RH + k] = __float2half_rn(v);
        }
        for (int idx = tid; idx < 128 * 24; idx += 256) {
            int tl = idx / 24, c = 64 + idx % 24;
            st[tl * RH + c] = __ushort_as_half(0);
        }
        __syncthreads();
        if (tid < 128) {
            float s = 0.f;
            for (int k = 0; k < 64; k++) {
                float v = z[((size_t)(b * 64 + k) << 10) + hw0 + tid];
                s += v * v;
            }
            g_znorm[(tile << 7) + tid] = s;
            st[tid * RH + 64] = __float2half_rn(1.0f);
        }
        __syncthreads();
        float4* dst = (float4*)(g_zh + (size_t)tile * 128 * RH);
        const float4* src = (const float4*)st;
        for (int i = tid; i < CHUNKH; i += 256) dst[i] = src[i];
        if (tile == 0 && tid == 0) { g_loss = 0.f; g_ent = 0.f; g_cu = 0; g_tick = 0; }
    } else {
        int sub = blk - 128;
        int n0 = sub << 7;
        for (int idx = tid; idx < 8192; idx += 256) {
            int nl = idx >> 6, k = idx & 63;
            float v = emb[(size_t)(n0 + nl) * 64 + k] * 4096.0f;   // exact scale
            st[nl * RH + k] = __float2half_rn(v);
        }
        for (int idx = tid; idx < 128 * 24; idx += 256) {
            int nl = idx / 24, c = 64 + idx % 24;
            st[nl * RH + c] = __ushort_as_half(0);
        }
        __syncthreads();
        if (tid < 128) {
            float s = 0.f;
            for (int k = 0; k < 64; k++) {
                float v = emb[(size_t)(n0 + tid) * 64 + k];
                s += v * v;
            }
            g_enorm[n0 + tid] = s;
            st[tid * RH + 64] = __float2half_rn(-2048.0f * s);
            g_counts[n0 + tid] = 0;
        }
        __syncthreads();
        float4* dst = (float4*)(g_eh + (size_t)sub * 128 * RH);
        const float4* src = (const float4*)st;
        for (int i = tid; i < CHUNKH; i += 256) dst[i] = src[i];
    }
}

// ---------------- single filter pass: M=256/CTA, N=8192/CTA, group-max table -------
// smem: A [0,45056) | B ring x4 (22528 each) -> total 135168
#define SM_F (ATILE + 4 * TILEH)

__global__ void __launch_bounds__(256, 1) k_filter() {
    extern __shared__ __align__(16) unsigned char sm[];
    uint32_t sb = smem_u32(sm);
    const uint32_t SA = sb, SBB = sb + ATILE;

    int tid = threadIdx.x, lane = tid & 31, wid = tid >> 5;
    int mw = wid & 3, nw = wid >> 2;        // 4 x 2 warp grid
    int mbase = mw * 64, nbw = nw * 64;     // warp tile 64 x 64

    int tile = blockIdx.x >> 1;             // 0..63 (256 tokens each)
    int half = blockIdx.x & 1;              // code half (8192 codes)
    int sub0 = half * 64;                   // first global 128-code subtile

    // prolog: A tile (256 rows) + B subtiles 0,1 of this half
    {
        const char* gz = (const char*)(g_zh + (size_t)tile * 256 * RH);
        for (int i = tid; i < CHUNKA; i += 256) CP_ASYNC16(SA + i * 16, gz + i * 16);
        const char* ge0 = (const char*)(g_eh + (size_t)sub0 * 128 * RH);
        for (int i = tid; i < CHUNKH; i += 256) CP_ASYNC16(SBB + i * 16, ge0 + i * 16);
        const char* ge1 = (const char*)(g_eh + (size_t)(sub0 + 1) * 128 * RH);
        for (int i = tid; i < CHUNKH; i += 256) CP_ASYNC16(SBB + TILEH + i * 16, ge1 + i * 16);
        CP_COMMIT(); CP_WAIT0();
    }
    __syncthreads();

    // ldmatrix addresses (conflict-free: 176B stride -> 8 distinct banks)
    uint32_t a_base = SA + (uint32_t)(mbase + (lane & 15)) * RBH + ((lane >> 4) & 1) * 16;
    // B x4 loads two ni (16 rows) at once
    uint32_t b_roff = (uint32_t)(nbw + ((lane >> 4) & 1) * 8 + (lane & 7)) * RBH
                    + ((lane >> 3) & 1) * 16;

    uint32_t acc[4][8][2];   // [mi][ni][c-reg], f16x2 each; acc = -2^11 * q

    for (int kp = 0; kp < 32; kp++) {
        int j0 = 2 * kp, j1 = j0 + 1;
        uint32_t s0 = SBB + (uint32_t)(j0 & 3) * TILEH;
        uint32_t s1 = SBB + (uint32_t)(j1 & 3) * TILEH;

        if (j0 + 2 < 64) {   // prefetch next pair
            const char* p0 = (const char*)(g_eh + (size_t)(sub0 + j0 + 2) * 128 * RH);
            uint32_t d0 = SBB + (uint32_t)((j0 + 2) & 3) * TILEH;
            for (int i = tid; i < CHUNKH; i += 256) CP_ASYNC16(d0 + i * 16, p0 + i * 16);
            const char* p1 = (const char*)(g_eh + (size_t)(sub0 + j1 + 2) * 128 * RH);
            uint32_t d1 = SBB + (uint32_t)((j1 + 2) & 3) * TILEH;
            for (int i = tid; i < CHUNKH; i += 256) CP_ASYNC16(d1 + i * 16, p1 + i * 16);
            CP_COMMIT();
        }

#pragma unroll
        for (int hf = 0; hf < 2; hf++) {
            int j = hf ? j1 : j0;
            uint32_t bb = (hf ? s1 : s0) + b_roff;

#pragma unroll
            for (int mi = 0; mi < 4; mi++)
#pragma unroll
                for (int ni = 0; ni < 8; ni++) { acc[mi][ni][0] = 0u; acc[mi][ni][1] = 0u; }

#pragma unroll
            for (int ks = 0; ks < 5; ks++) {
                uint32_t ah[4][4], bq[4][4];
#pragma unroll
                for (int mi = 0; mi < 4; mi++)
                    LDSM_X4(ah[mi], a_base + mi * 16 * RBH + ks * 32);
#pragma unroll
                for (int np = 0; np < 4; np++)
                    LDSM_X4(bq[np], bb + np * 16 * RBH + ks * 32);
#pragma unroll
                for (int mi = 0; mi < 4; mi++)
#pragma unroll
                    for (int np = 0; np < 4; np++) {
                        mma16816h(acc[mi][np * 2],     ah[mi], &bq[np][0]);
                        mma16816h(acc[mi][np * 2 + 1], ah[mi], &bq[np][2]);
                    }
            }

            // group-max epilogue: per row, max over this warp's 64 cols -> table
#pragma unroll
            for (int mi = 0; mi < 4; mi++) {
#pragma unroll
                for (int rh = 0; rh < 2; rh++) {
                    __half2 m01 = __hmax2(u2h(acc[mi][0][rh]), u2h(acc[mi][1][rh]));
                    __half2 m23 = __hmax2(u2h(acc[mi][2][rh]), u2h(acc[mi][3][rh]));
                    __half2 m45 = __hmax2(u2h(acc[mi][4][rh]), u2h(acc[mi][5][rh]));
                    __half2 m67 = __hmax2(u2h(acc[mi][6][rh]), u2h(acc[mi][7][rh]));
                    __half2 m = __hmax2(__hmax2(m01, m23), __hmax2(m45, m67));
                    float f = fmaxf(__low2float(m), __high2float(m));
                    f = fmaxf(f, __shfl_xor_sync(0xffffffffu, f, 1));
                    f = fmaxf(f, __shfl_xor_sync(0xffffffffu, f, 2));
                    if ((lane & 3) == 0) {
                        int row = mbase + mi * 16 + rh * 8 + (lane >> 2);
                        int t = (tile << 8) + row;
                        int entry = (half << 7) + (j << 1) + nw;
                        g_gmax[(size_t)t * 256 + entry] = f;
                    }
                }
            }
        }

        CP_WAIT0();
        __syncthreads();
    }
}

// ---------------- refine: scan group table, exact fp32 over flagged groups ---------
__global__ void k_refine(const float* __restrict__ z, const float* __restrict__ emb,
                         float* __restrict__ out) {
    __shared__ float zs[8][64];
    int w = threadIdx.x >> 5, lane = threadIdx.x & 31;
    int t = blockIdx.x * 8 + w;
    int b = t >> 10, hw = t & 1023;
    zs[w][lane]      = z[((size_t)(b * 64 + lane) << 10) + hw];
    zs[w][lane + 32] = z[((size_t)(b * 64 + lane + 32) << 10) + hw];
    __syncwarp();
    float zn = g_znorm[t];

    // load 256 group maxes (8 per lane), find global max
    float v[8];
#pragma unroll
    for (int i = 0; i < 8; i++) v[i] = g_gmax[(size_t)t * 256 + i * 32 + lane];
    float gm = v[0];
#pragma unroll
    for (int i = 1; i < 8; i++) gm = fmaxf(gm, v[i]);
#pragma unroll
    for (int off = 16; off > 0; off >>= 1)
        gm = fmaxf(gm, __shfl_xor_sync(0xffffffffu, gm, off));
    float thr = gm - fmaf(sqrtf(zn), 2048.0f * MK1, 2048.0f * MK2);

    float bd = 3.0e38f; int bn = 0x7fffffff;
#pragma unroll
    for (int i = 0; i < 8; i++) {
        unsigned msk = __ballot_sync(0xffffffffu, v[i] >= thr);
        while (msk) {
            int src = __ffs(msk) - 1;
            msk &= msk - 1;
            int e = i * 32 + src;
            int hh = e >> 7, j = (e >> 1) & 63, nwv = e & 1;
            int n0 = (hh << 13) + (j << 7) + (nwv << 6);
            // exact fp32 distances for the 64 codes of this group (2 per lane)
#pragma unroll
            for (int c = 0; c < 2; c++) {
                int n = n0 + lane * 2 + c;
                const float* er = emb + (size_t)n * 64;
                float acc = 0.f;
#pragma unroll
                for (int k = 0; k < 64; k++) acc = fmaf(zs[w][k], er[k], acc);
                float d = __fsub_rn(__fadd_rn(zn, g_enorm[n]), __fmul_rn(2.0f, acc));
                if (d < bd || (d == bd && n < bn)) { bd = d; bn = n; }
            }
        }
    }
#pragma unroll
    for (int off = 16; off > 0; off >>= 1) {
        float od = __shfl_xor_sync(0xffffffffu, bd, off);
        int   on = __shfl_xor_sync(0xffffffffu, bn, off);
        if (od < bd || (od == bd && on < bn)) { bd = od; bn = on; }
    }
    if (lane == 0) {
        g_idx[t] = bn;
        out[1048579 + t] = (float)bn;
        atomicAdd(&g_counts[bn], 1);
    }
}

// ---------------- z_q gather + loss accumulation ----------------
__global__ void k_zq(const float* __restrict__ z, const float* __restrict__ emb,
                     float* __restrict__ out) {
    int p = blockIdx.x;            // 1024 planes = (b,c)
    int b = p >> 6, c = p & 63;
    int tid = threadIdx.x;         // 256
    float ls = 0.f;
    for (int hw = tid; hw < 1024; hw += 256) {
        int t = (b << 10) + hw;
        int id = g_idx[t];
        float v  = emb[(size_t)id * 64 + c];
        float zv = z[(size_t)p * 1024 + hw];
        out[(size_t)p * 1024 + hw] = v;
        float df = v - zv;
        ls += df * df;
    }
    __shared__ float red[8];
    for (int o = 16; o > 0; o >>= 1) ls += __shfl_down_sync(0xffffffff, ls, o);
    if ((tid & 31) == 0) red[tid >> 5] = ls;
    __syncthreads();
    if (tid == 0) {
        float s = 0.f;
        for (int w = 0; w < 8; w++) s += red[w];
        atomicAdd(&g_loss, s);
    }
}

// ---------------- entropy (parallel) + final scalar writes (ticket) ----------------
__global__ void k_ent(float* __restrict__ out) {
    int tid = threadIdx.x;                      // 1024, grid 16
    int n = blockIdx.x * 1024 + tid;
    int c = g_counts[n];
    float avg = (float)c * (1.0f / 16384.0f);
    float term = avg * logf(avg + 1e-10f);
    int cu = (c > 0) ? 1 : 0;
    for (int o = 16; o > 0; o >>= 1) {
        term += __shfl_down_sync(0xffffffffu, term, o);
        cu   += __shfl_down_sync(0xffffffffu, cu, o);
    }
    __shared__ float se[32]; __shared__ int sc[32];
    if ((tid & 31) == 0) { se[tid >> 5] = term; sc[tid >> 5] = cu; }
    __syncthreads();
    if (tid == 0) {
        float s = 0.f; int k = 0;
        for (int w = 0; w < 32; w++) { s += se[w]; k += sc[w]; }
        atomicAdd(&g_ent, s);
        atomicAdd(&g_cu, k);
        __threadfence();
        int tk = atomicAdd(&g_tick, 1);
        if (tk == 15) {
            out[1048576] = g_loss * (1.0f + BETA) / 1048576.0f;
            out[1048577] = expf(-g_ent);
            out[1048578] = (float)g_cu;
        }
    }
}

// ---------------- launch ----------------
extern "C" void kernel_launch(void* const* d_in, const int* in_sizes, int n_in,
                              void* d_out, int out_size) {
    const float* z   = (const float*)d_in[0];   // (16,64,32,32)
    const float* emb = (const float*)d_in[1];   // (16384,64)
    float* out = (float*)d_out;

    cudaFuncSetAttribute(k_split,  cudaFuncAttributeMaxDynamicSharedMemorySize, TILEH);
    cudaFuncSetAttribute(k_filter, cudaFuncAttributeMaxDynamicSharedMemorySize, SM_F);

    k_split<<<256, 256, TILEH>>>(z, emb);
    k_filter<<<128, 256, SM_F>>>();
    k_refine<<<2048, 256>>>(z, emb, out);
    k_zq<<<1024, 256>>>(z, emb, out);
    k_ent<<<16, 1024>>>(out);
}

// round 16
// speedup vs baseline: 1.5100x; 1.5100x over previous
#include <cuda_runtime.h>
#include <cuda_fp16.h>
#include <math.h>
#include <stdint.h>

#define NT 16384
#define NE 16384
#define BETA 0.25f

#define RH  88                      // halves per padded row (80 data, 8 pad)
#define RBH 176                     // bytes per row (11*16 -> conflict-free ldmatrix)
#define TILEH (128 * RBH)           // 22528
#define CHUNKH (TILEH / 16)         // 1408

#define MK1 4.0e-4f                 // q-domain margin slope * sqrt(zn)  (validated)
#define MK2 7.0e-3f                 // q-domain margin offset            (validated)

// ---------------- static device scratch ----------------
__device__ __half g_zh[16384 * RH];   // [zh | 1 | 0...] padded rows
__device__ __half g_eh[16384 * RH];   // [Eh | -2048*en | 0...] (E = 4096*e)
__device__ float g_enorm[NE];
__device__ float g_znorm[NT];
__device__ float g_gmax[(size_t)512 * NT];  // [entry][token]: 32-code-group acc max
__device__ int   g_idx[NT];
__device__ int   g_counts[NE];
__device__ float g_loss;
__device__ float g_ent;
__device__ int   g_cu;
__device__ int   g_tick;

// ---------------- helpers ----------------
__device__ __forceinline__ uint32_t smem_u32(const void* p) {
    uint32_t a;
    asm("{ .reg .u64 t; cvta.to.shared.u64 t, %1; cvt.u32.u64 %0, t; }" : "=r"(a) : "l"(p));
    return a;
}
__device__ __forceinline__ __half2 u2h(uint32_t u) {
    return *reinterpret_cast<__half2*>(&u);
}

#define CP_ASYNC16(dst_u32, src_ptr) \
    asm volatile("cp.async.cg.shared.global [%0], [%1], 16;\n" :: "r"(dst_u32), "l"(src_ptr))
#define CP_COMMIT()  asm volatile("cp.async.commit_group;\n" ::: "memory")
#define CP_WAIT0()   asm volatile("cp.async.wait_group 0;\n" ::: "memory")

#define LDSM_X4(r, addr) \
    asm volatile("ldmatrix.sync.aligned.m8n8.x4.shared.b16 {%0,%1,%2,%3}, [%4];" \
        : "=r"((r)[0]), "=r"((r)[1]), "=r"((r)[2]), "=r"((r)[3]) : "r"(addr))
#define LDSM_X2(r, addr) \
    asm volatile("ldmatrix.sync.aligned.m8n8.x2.shared.b16 {%0,%1}, [%2];" \
        : "=r"((r)[0]), "=r"((r)[1]) : "r"(addr))

// fp16-accumulate mma (double-rate vs f32-acc)
__device__ __forceinline__ void mma16816h(uint32_t* c, const uint32_t* a, const uint32_t* b) {
    asm volatile(
        "mma.sync.aligned.m16n8k16.row.col.f16.f16.f16.f16 "
        "{%0,%1}, {%2,%3,%4,%5}, {%6,%7}, {%0,%1};"
        : "+r"(c[0]), "+r"(c[1])
        : "r"(a[0]), "r"(a[1]), "r"(a[2]), "r"(a[3]), "r"(b[0]), "r"(b[1]));
}

// ---------------- prep: h tiles with folded norm column; zero state ----------------
__global__ void k_split(const float* __restrict__ z, const float* __restrict__ emb) {
    extern __shared__ __half st[];          // 128*RH halves = 22528 B
    int blk = blockIdx.x;                   // 0..127 z tiles, 128..255 e subtiles
    int tid = threadIdx.x;                  // 256
    if (blk < 128) {
        int tile = blk;
        int b = tile >> 3, hw0 = (tile & 7) << 7;
        for (int idx = tid; idx < 8192; idx += 256) {
            int k = idx >> 7, tl = idx & 127;
            float v = z[((size_t)(b * 64 + k) << 10) + hw0 + tl];
            st[tl * RH + k] = __float2half_rn(v);
        }
        for (int idx = tid; idx < 128 * 24; idx += 256) {
            int tl = idx / 24, c = 64 + idx % 24;
            st[tl * RH + c] = __ushort_as_half(0);
        }
        __syncthreads();
        if (tid < 128) {
            float s = 0.f;
            for (int k = 0; k < 64; k++) {
                float v = z[((size_t)(b * 64 + k) << 10) + hw0 + tid];
                s += v * v;
            }
            g_znorm[(tile << 7) + tid] = s;
            st[tid * RH + 64] = __float2half_rn(1.0f);
        }
        __syncthreads();
        float4* dst = (float4*)(g_zh + (size_t)tile * 128 * RH);
        const float4* src = (const float4*)st;
        for (int i = tid; i < CHUNKH; i += 256) dst[i] = src[i];
        if (tile == 0 && tid == 0) { g_loss = 0.f; g_ent = 0.f; g_cu = 0; g_tick = 0; }
    } else {
        int sub = blk - 128;
        int n0 = sub << 7;
        for (int idx = tid; idx < 8192; idx += 256) {
            int nl = idx >> 6, k = idx & 63;
            float v = emb[(size_t)(n0 + nl) * 64 + k] * 4096.0f;   // exact scale
            st[nl * RH + k] = __float2half_rn(v);
        }
        for (int idx = tid; idx < 128 * 24; idx += 256) {
            int nl = idx / 24, c = 64 + idx % 24;
            st[nl * RH + c] = __ushort_as_half(0);
        }
        __syncthreads();
        if (tid < 128) {
            float s = 0.f;
            for (int k = 0; k < 64; k++) {
                float v = emb[(size_t)(n0 + tid) * 64 + k];
                s += v * v;
            }
            g_enorm[n0 + tid] = s;
            st[tid * RH + 64] = __float2half_rn(-2048.0f * s);
            g_counts[n0 + tid] = 0;
        }
        __syncthreads();
        float4* dst = (float4*)(g_eh + (size_t)sub * 128 * RH);
        const float4* src = (const float4*)st;
        for (int i = tid; i < CHUNKH; i += 256) dst[i] = src[i];
    }
}

// hh+norm mma over K=80 tiles; acc[mi][ni][rh] = half2 (2 cols); acc = -2^11 * q
__device__ __forceinline__ void mma_phase_h16(uint32_t a_base, uint32_t b_base,
                                              uint32_t acc[4][4][2]) {
#pragma unroll
    for (int mi = 0; mi < 4; mi++)
#pragma unroll
        for (int ni = 0; ni < 4; ni++) { acc[mi][ni][0] = 0u; acc[mi][ni][1] = 0u; }
#pragma unroll
    for (int ks = 0; ks < 5; ks++) {
        uint32_t ah[4][4], bh[4][2];
#pragma unroll
        for (int mi = 0; mi < 4; mi++)
            LDSM_X4(ah[mi], a_base + mi * 16 * RBH + ks * 32);
#pragma unroll
        for (int ni = 0; ni < 4; ni++)
            LDSM_X2(bh[ni], b_base + ni * 8 * RBH + ks * 32);
#pragma unroll
        for (int mi = 0; mi < 4; mi++)
#pragma unroll
            for (int ni = 0; ni < 4; ni++)
                mma16816h(acc[mi][ni], ah[mi], bh[ni]);
    }
}

// ---------------- single pass: group-max table (R14 k_min + table store) -----------
// smem: A [0,22528) | B ring x4  (total 112640)
#define SM_F (5 * TILEH)

__global__ void __launch_bounds__(256, 1) k_min() {
    extern __shared__ __align__(16) unsigned char sm[];
    uint32_t sb = smem_u32(sm);
    const uint32_t SA = sb, SBB = sb + TILEH;

    int tid = threadIdx.x, lane = tid & 31, wid = tid >> 5;
    int mw = wid & 1, nw = wid >> 1;        // 2 x 4 warp grid
    int mbase = mw * 64, nbw = nw * 32;     // warp tile 64 x 32

    {
        const char* gz = (const char*)(g_zh + (size_t)blockIdx.x * 128 * RH);
        for (int i = tid; i < CHUNKH; i += 256) CP_ASYNC16(SA + i * 16, gz + i * 16);
        const char* ge0 = (const char*)g_eh;
        for (int i = tid; i < CHUNKH; i += 256) CP_ASYNC16(SBB + i * 16, ge0 + i * 16);
        const char* ge1 = (const char*)(g_eh + (size_t)128 * RH);
        for (int i = tid; i < CHUNKH; i += 256) CP_ASYNC16(SBB + TILEH + i * 16, ge1 + i * 16);
        CP_COMMIT(); CP_WAIT0();
    }
    __syncthreads();

    uint32_t a_base = SA + (uint32_t)(mbase + (lane & 15)) * RBH + ((lane >> 4) & 1) * 16;
    uint32_t b_roff = (uint32_t)(nbw + (lane & 7)) * RBH + ((lane >> 3) & 1) * 16;

    int tbase = (blockIdx.x << 7) + mbase;
    uint32_t acc[4][4][2];

    for (int kp = 0; kp < 64; kp++) {
        int j0 = 2 * kp, j1 = j0 + 1;
        uint32_t s0 = SBB + (uint32_t)(j0 & 3) * TILEH;
        uint32_t s1 = SBB + (uint32_t)(j1 & 3) * TILEH;

        if (j0 + 2 < 128) {
            const char* p0 = (const char*)(g_eh + (size_t)(j0 + 2) * 128 * RH);
            uint32_t d0 = SBB + (uint32_t)((j0 + 2) & 3) * TILEH;
            for (int i = tid; i < CHUNKH; i += 256) CP_ASYNC16(d0 + i * 16, p0 + i * 16);
            const char* p1 = (const char*)(g_eh + (size_t)(j1 + 2) * 128 * RH);
            uint32_t d1 = SBB + (uint32_t)((j1 + 2) & 3) * TILEH;
            for (int i = tid; i < CHUNKH; i += 256) CP_ASYNC16(d1 + i * 16, p1 + i * 16);
            CP_COMMIT();
        }

#pragma unroll
        for (int half = 0; half < 2; half++) {
            int j = half ? j1 : j0;
            uint32_t bb = (half ? s1 : s0) + b_roff;
            mma_phase_h16(a_base, bb, acc);
            // group-max epilogue: per row, max over this warp's 32 cols -> table.
            // entry-major layout => the 8 quad-leader stores hit 8 consecutive floats.
            float* gdst = &g_gmax[(size_t)(j * 4 + nw) * NT + tbase];
#pragma unroll
            for (int mi = 0; mi < 4; mi++) {
#pragma unroll
                for (int rh = 0; rh < 2; rh++) {
                    __half2 m = __hmax2(__hmax2(u2h(acc[mi][0][rh]), u2h(acc[mi][1][rh])),
                                        __hmax2(u2h(acc[mi][2][rh]), u2h(acc[mi][3][rh])));
                    float f = fmaxf(__low2float(m), __high2float(m));
                    f = fmaxf(f, __shfl_xor_sync(0xffffffffu, f, 1));
                    f = fmaxf(f, __shfl_xor_sync(0xffffffffu, f, 2));
                    if ((lane & 3) == 0)
                        gdst[mi * 16 + rh * 8 + (lane >> 2)] = f;
                }
            }
        }

        CP_WAIT0();
        __syncthreads();
    }
}

// ---------------- refine: scan table, exact fp32 over flagged 32-code groups -------
__global__ void k_refine(const float* __restrict__ z, const float* __restrict__ emb,
                         float* __restrict__ out) {
    __shared__ float zs[8][64];
    __shared__ float stbl[8][512];
    int tid = threadIdx.x;
    int w = tid >> 5, lane = tid & 31;
    int t0 = blockIdx.x * 8;
    int t = t0 + w;
    int b = t >> 10, hw = t & 1023;

    // stage table slices coalesced: entry-major gmem => 8-token runs contiguous
    for (int i = tid; i < 4096; i += 256) {
        int e = i >> 3, tt = i & 7;
        stbl[tt][e] = g_gmax[(size_t)e * NT + t0 + tt];
    }
    zs[w][lane]      = z[((size_t)(b * 64 + lane) << 10) + hw];
    zs[w][lane + 32] = z[((size_t)(b * 64 + lane + 32) << 10) + hw];
    __syncthreads();

    float zn = g_znorm[t];

    float v[16];
#pragma unroll
    for (int i = 0; i < 16; i++) v[i] = stbl[w][i * 32 + lane];
    float gm = v[0];
#pragma unroll
    for (int i = 1; i < 16; i++) gm = fmaxf(gm, v[i]);
#pragma unroll
    for (int off = 16; off > 0; off >>= 1)
        gm = fmaxf(gm, __shfl_xor_sync(0xffffffffu, gm, off));
    // acc >= thr  <=>  q <= qmin + M
    float thr = gm - fmaf(sqrtf(zn), 2048.0f * MK1, 2048.0f * MK2);

    float bd = 3.0e38f; int bn = 0x7fffffff;
#pragma unroll
    for (int i = 0; i < 16; i++) {
        unsigned msk = __ballot_sync(0xffffffffu, v[i] >= thr);
        while (msk) {
            int src = __ffs(msk) - 1;
            msk &= msk - 1;
            int e = i * 32 + src;                 // entry = j*4 + nw
            int n = (e >> 2) * 128 + (e & 3) * 32 + lane;   // 1 code per lane
            const float* er = emb + (size_t)n * 64;
            float acc = 0.f;
#pragma unroll
            for (int k = 0; k < 64; k++) acc = fmaf(zs[w][k], er[k], acc);
            float d = __fsub_rn(__fadd_rn(zn, g_enorm[n]), __fmul_rn(2.0f, acc));
            if (d < bd || (d == bd && n < bn)) { bd = d; bn = n; }
        }
    }
#pragma unroll
    for (int off = 16; off > 0; off >>= 1) {
        float od = __shfl_xor_sync(0xffffffffu, bd, off);
        int   on = __shfl_xor_sync(0xffffffffu, bn, off);
        if (od < bd || (od == bd && on < bn)) { bd = od; bn = on; }
    }
    if (lane == 0) {
        g_idx[t] = bn;
        out[1048579 + t] = (float)bn;
        atomicAdd(&g_counts[bn], 1);
    }
}

// ---------------- z_q gather + loss accumulation ----------------
__global__ void k_zq(const float* __restrict__ z, const float* __restrict__ emb,
                     float* __restrict__ out) {
    int p = blockIdx.x;            // 1024 planes = (b,c)
    int b = p >> 6, c = p & 63;
    int tid = threadIdx.x;         // 256
    float ls = 0.f;
    for (int hw = tid; hw < 1024; hw += 256) {
        int t = (b << 10) + hw;
        int id = g_idx[t];
        float v  = emb[(size_t)id * 64 + c];
        float zv = z[(size_t)p * 1024 + hw];
        out[(size_t)p * 1024 + hw] = v;
        float df = v - zv;
        ls += df * df;
    }
    __shared__ float red[8];
    for (int o = 16; o > 0; o >>= 1) ls += __shfl_down_sync(0xffffffff, ls, o);
    if ((tid & 31) == 0) red[tid >> 5] = ls;
    __syncthreads();
    if (tid == 0) {
        float s = 0.f;
        for (int w = 0; w < 8; w++) s += red[w];
        atomicAdd(&g_loss, s);
    }
}

// ---------------- entropy (parallel) + final scalar writes (ticket) ----------------
__global__ void k_ent(float* __restrict__ out) {
    int tid = threadIdx.x;                      // 1024, grid 16
    int n = blockIdx.x * 1024 + tid;
    int c = g_counts[n];
    float avg = (float)c * (1.0f / 16384.0f);
    float term = avg * logf(avg + 1e-10f);
    int cu = (c > 0) ? 1 : 0;
    for (int o = 16; o > 0; o >>= 1) {
        term += __shfl_down_sync(0xffffffffu, term, o);
        cu   += __shfl_down_sync(0xffffffffu, cu, o);
    }
    __shared__ float se[32]; __shared__ int sc[32];
    if ((tid & 31) == 0) { se[tid >> 5] = term; sc[tid >> 5] = cu; }
    __syncthreads();
    if (tid == 0) {
        float s = 0.f; int k = 0;
        for (int w = 0; w < 32; w++) { s += se[w]; k += sc[w]; }
        atomicAdd(&g_ent, s);
        atomicAdd(&g_cu, k);
        __threadfence();
        int tk = atomicAdd(&g_tick, 1);
        if (tk == 15) {
            out[1048576] = g_loss * (1.0f + BETA) / 1048576.0f;
            out[1048577] = expf(-g_ent);
            out[1048578] = (float)g_cu;
        }
    }
}

// ---------------- launch ----------------
extern "C" void kernel_launch(void* const* d_in, const int* in_sizes, int n_in,
                              void* d_out, int out_size) {
    const float* z   = (const float*)d_in[0];   // (16,64,32,32)
    const float* emb = (const float*)d_in[1];   // (16384,64)
    float* out = (float*)d_out;

    cudaFuncSetAttribute(k_split, cudaFuncAttributeMaxDynamicSharedMemorySize, TILEH);
    cudaFuncSetAttribute(k_min,   cudaFuncAttributeMaxDynamicSharedMemorySize, SM_F);

    k_split<<<256, 256, TILEH>>>(z, emb);
    k_min<<<128, 256, SM_F>>>();
    k_refine<<<2048, 256>>>(z, emb, out);
    k_zq<<<1024, 256>>>(z, emb, out);
    k_ent<<<16, 1024>>>(out);
}

// round 17
// speedup vs baseline: 2.2128x; 1.4654x over previous
#include <cuda_runtime.h>
#include <cuda_fp16.h>
#include <math.h>
#include <stdint.h>

#define NT 16384
#define NE 16384
#define BETA 0.25f

#define RS2 136                     // halves per padded row (128 data + 8 pad)
#define RB2 272                     // bytes per row (17*16 -> conflict-free ldmatrix)
#define TILE2_BYTES (128 * RB2)     // 34816
#define CHUNK2 (TILE2_BYTES / 16)   // 2176

// ---------------- static device scratch ----------------
__device__ __half g_zf[16384 * RS2];  // A = [h_z | l_z], padded rows
__device__ __half g_ef[16384 * RS2];  // B = [h_E | l_E], E = 4096*e
__device__ float g_enorm[NE];
__device__ float g_znorm[NT];
__device__ int   g_idx[NT];
__device__ int   g_counts[NE];
__device__ float g_loss;
__device__ float g_ent;
__device__ int   g_cu;
__device__ int   g_tick;

// ---------------- helpers ----------------
__device__ __forceinline__ uint32_t smem_u32(const void* p) {
    uint32_t a;
    asm("{ .reg .u64 t; cvta.to.shared.u64 t, %1; cvt.u32.u64 %0, t; }" : "=r"(a) : "l"(p));
    return a;
}
__device__ __forceinline__ void split2h(float v, __half& h, __half& l) {
    __half hh = __float2half_rn(v);
    float r = __fsub_rn(v, __half2float(hh));   // exact
    h = hh; l = __float2half_rn(r);
}

// ---- bulk copy + mbarrier (base sm_90 PTX; compiles at compute_100) ----
__device__ __forceinline__ void mbar_init(uint32_t a, uint32_t cnt) {
    asm volatile("mbarrier.init.shared.b64 [%0], %1;" :: "r"(a), "r"(cnt) : "memory");
}
__device__ __forceinline__ void mbar_expect_tx(uint32_t a, uint32_t bytes) {
    asm volatile("mbarrier.arrive.expect_tx.shared.b64 _, [%0], %1;"
                 :: "r"(a), "r"(bytes) : "memory");
}
__device__ __forceinline__ void mbar_wait(uint32_t a, uint32_t parity) {
    asm volatile(
        "{\n\t.reg .pred P;\n"
        "WAITL_%=:\n\t"
        "mbarrier.try_wait.parity.shared.b64 P, [%0], %1;\n\t"
        "@P bra WDONE_%=;\n\t"
        "bra WAITL_%=;\n"
        "WDONE_%=:\n\t}"
        :: "r"(a), "r"(parity) : "memory");
}
__device__ __forceinline__ void bulk_cp(uint32_t dst, const void* src, uint32_t bytes,
                                        uint32_t mbar) {
    asm volatile(
        "cp.async.bulk.shared::cta.global.mbarrier::complete_tx::bytes [%0], [%1], %2, [%3];"
        :: "r"(dst), "l"(src), "r"(bytes), "r"(mbar) : "memory");
}

#define CP_ASYNC16(dst_u32, src_ptr) \
    asm volatile("cp.async.cg.shared.global [%0], [%1], 16;\n" :: "r"(dst_u32), "l"(src_ptr))
#define CP_COMMIT()  asm volatile("cp.async.commit_group;\n" ::: "memory")
#define CP_WAIT0()   asm volatile("cp.async.wait_group 0;\n" ::: "memory")

#define LDSM_X4(r, addr) \
    asm volatile("ldmatrix.sync.aligned.m8n8.x4.shared.b16 {%0,%1,%2,%3}, [%4];" \
        : "=r"((r)[0]), "=r"((r)[1]), "=r"((r)[2]), "=r"((r)[3]) : "r"(addr))
#define LDSM_X2(r, addr) \
    asm volatile("ldmatrix.sync.aligned.m8n8.x2.shared.b16 {%0,%1}, [%2];" \
        : "=r"((r)[0]), "=r"((r)[1]) : "r"(addr))

__device__ __forceinline__ void mma16816(float* c, const uint32_t* a, const uint32_t* b) {
    asm volatile(
        "mma.sync.aligned.m16n8k16.row.col.f32.f16.f16.f32 "
        "{%0,%1,%2,%3}, {%4,%5,%6,%7}, {%8,%9}, {%0,%1,%2,%3};"
        : "+f"(c[0]), "+f"(c[1]), "+f"(c[2]), "+f"(c[3])
        : "r"(a[0]), "r"(a[1]), "r"(a[2]), "r"(a[3]), "r"(b[0]), "r"(b[1]));
}

// ---------------- prep (fused): split z and E=4096*e; norms; zero state --------------
__global__ void k_split(const float* __restrict__ z, const float* __restrict__ emb) {
    extern __shared__ __half st[];          // 128 * RS2 halves = 34816 B
    int blk = blockIdx.x;                   // 0..127 z tiles, 128..255 e subtiles
    int tid = threadIdx.x;                  // 256
    if (blk < 128) {
        int tile = blk;
        int b = tile >> 3, hw0 = (tile & 7) << 7;
        for (int idx = tid; idx < 8192; idx += 256) {
            int k = idx >> 7, tl = idx & 127;
            float v = z[((size_t)(b * 64 + k) << 10) + hw0 + tl];
            __half h, l; split2h(v, h, l);
            st[tl * RS2 + k]      = h;
            st[tl * RS2 + 64 + k] = l;
        }
        __syncthreads();
        float4* dst = (float4*)(g_zf + (size_t)tile * 128 * RS2);
        const float4* src = (const float4*)st;
        for (int i = tid; i < CHUNK2; i += 256) dst[i] = src[i];
        if (tid < 128) {
            float s = 0.f;
            for (int k = 0; k < 64; k++) {
                float v = z[((size_t)(b * 64 + k) << 10) + hw0 + tid];
                s += v * v;
            }
            g_znorm[(tile << 7) + tid] = s;
        }
        if (tile == 0 && tid == 0) { g_loss = 0.f; g_ent = 0.f; g_cu = 0; g_tick = 0; }
    } else {
        int sub = blk - 128;
        int n0 = sub << 7;
        for (int idx = tid; idx < 8192; idx += 256) {
            int nl = idx >> 6, k = idx & 63;
            float v = emb[(size_t)(n0 + nl) * 64 + k] * 4096.0f;   // exact scale
            __half h, l; split2h(v, h, l);
            st[nl * RS2 + k]      = h;
            st[nl * RS2 + 64 + k] = l;
        }
        __syncthreads();
        float4* dst = (float4*)(g_ef + (size_t)sub * 128 * RS2);
        const float4* src = (const float4*)st;
        for (int i = tid; i < CHUNK2; i += 256) dst[i] = src[i];
        if (tid < 128) {
            float s = 0.f;
            for (int k = 0; k < 64; k++) {
                float v = emb[(size_t)(n0 + tid) * 64 + k];
                s += v * v;
            }
            g_enorm[n0 + tid] = s;
            g_counts[n0 + tid] = 0;
        }
    }
}

// ---------------- building blocks (byte-identical to R6) ----------------
__device__ __forceinline__ void load_en(int j, int nbw, int lane, float en[8]) {
#pragma unroll
    for (int ni = 0; ni < 4; ni++) {
        int c0 = nbw + ni * 8 + (lane & 3) * 2;
        en[ni * 2]     = __ldg(&g_enorm[(j << 7) + c0]);
        en[ni * 2 + 1] = __ldg(&g_enorm[(j << 7) + c0 + 1]);
    }
}

// 3-product (hh + lh + hl) mma over K=128 stored tiles; fragments register-cached.
__device__ __forceinline__ void mma_phase(uint32_t a_base, uint32_t b_base,
                                          float acc[4][4][4]) {
#pragma unroll
    for (int mi = 0; mi < 4; mi++)
#pragma unroll
        for (int ni = 0; ni < 4; ni++)
#pragma unroll
            for (int q = 0; q < 4; q++) acc[mi][ni][q] = 0.f;
#pragma unroll
    for (int ks = 0; ks < 4; ks++) {
        uint32_t ah[4][4], al[4][4], bh[4][2], bl[4][2];
#pragma unroll
        for (int mi = 0; mi < 4; mi++) {
            LDSM_X4(ah[mi], a_base + mi * 16 * RB2 + ks * 32);
            LDSM_X4(al[mi], a_base + mi * 16 * RB2 + 128 + ks * 32);
        }
#pragma unroll
        for (int ni = 0; ni < 4; ni++) {
            LDSM_X2(bh[ni], b_base + ni * 8 * RB2 + ks * 32);
            LDSM_X2(bl[ni], b_base + ni * 8 * RB2 + 128 + ks * 32);
        }
#pragma unroll
        for (int mi = 0; mi < 4; mi++)
#pragma unroll
            for (int ni = 0; ni < 4; ni++)
                mma16816(acc[mi][ni], ah[mi], bh[ni]);
#pragma unroll
        for (int mi = 0; mi < 4; mi++)
#pragma unroll
            for (int ni = 0; ni < 4; ni++)
                mma16816(acc[mi][ni], al[mi], bh[ni]);
#pragma unroll
        for (int mi = 0; mi < 4; mi++)
#pragma unroll
            for (int ni = 0; ni < 4; ni++)
                mma16816(acc[mi][ni], ah[mi], bl[ni]);
    }
}

// d = fl( fl(zn+en) - acc*2^-11 ), single FFMA rounding (acc*2^-11 exact).
__device__ __forceinline__ void epi_phase(const float acc[4][4][4], const float en[8],
                                          const float zn[8], int j, int nbw, int lane,
                                          float bv[8], int bi[8]) {
#pragma unroll
    for (int mi = 0; mi < 4; mi++) {
#pragma unroll
        for (int ni = 0; ni < 4; ni++) {
            int n0 = (j << 7) + nbw + ni * 8 + (lane & 3) * 2;
            float c00 = __fadd_rn(zn[mi * 2],     en[ni * 2]);
            float c01 = __fadd_rn(zn[mi * 2],     en[ni * 2 + 1]);
            float c10 = __fadd_rn(zn[mi * 2 + 1], en[ni * 2]);
            float c11 = __fadd_rn(zn[mi * 2 + 1], en[ni * 2 + 1]);
            float d0 = fmaf(acc[mi][ni][0], -0x1p-11f, c00);
            float d1 = fmaf(acc[mi][ni][1], -0x1p-11f, c01);
            float d2 = fmaf(acc[mi][ni][2], -0x1p-11f, c10);
            float d3 = fmaf(acc[mi][ni][3], -0x1p-11f, c11);
            if (d0 < bv[mi * 2])     { bv[mi * 2]     = d0; bi[mi * 2]     = n0; }
            if (d1 < bv[mi * 2])     { bv[mi * 2]     = d1; bi[mi * 2]     = n0 + 1; }
            if (d2 < bv[mi * 2 + 1]) { bv[mi * 2 + 1] = d2; bi[mi * 2 + 1] = n0; }
            if (d3 < bv[mi * 2 + 1]) { bv[mi * 2 + 1] = d3; bi[mi * 2 + 1] = n0 + 1; }
        }
    }
}

// ---------------- main: R6 GEMM with cp.async.bulk B feed ----------------
// smem: A [0,34816) | B0 | B1 | mbar[2] at 3*TILE2_BYTES
#define SM_TOT (3 * TILE2_BYTES + 64)

__global__ void __launch_bounds__(256, 1) k_mma(float* __restrict__ out) {
    extern __shared__ __align__(128) unsigned char sm[];
    uint32_t sb = smem_u32(sm);
    const uint32_t SA = sb, SB0 = sb + TILE2_BYTES, SB1 = sb + 2 * TILE2_BYTES;
    const uint32_t MB0 = sb + 3 * TILE2_BYTES, MB1 = MB0 + 8;

    int tid = threadIdx.x, lane = tid & 31, wid = tid >> 5;
    int mw = wid & 1, nw = wid >> 1;        // 2 x 4 warp grid
    int mbase = mw * 64, nbw = nw * 32;     // warp tile 64 x 32

    if (tid == 0) { mbar_init(MB0, 1); mbar_init(MB1, 1); }
    __syncthreads();

    // prolog: A + B0 on bar0 (one expect covering both bulks), B1 on bar1
    if (tid == 0) {
        mbar_expect_tx(MB0, TILE2_BYTES * 2);
        bulk_cp(SA,  g_zf + (size_t)blockIdx.x * 128 * RS2, TILE2_BYTES, MB0);
        bulk_cp(SB0, g_ef,                                  TILE2_BYTES, MB0);
        mbar_expect_tx(MB1, TILE2_BYTES);
        bulk_cp(SB1, g_ef + (size_t)128 * RS2,              TILE2_BYTES, MB1);
    }

    // per-thread rows: r = mbase + mi*16 + rh*8 + (lane>>2)
    float zn[8];
#pragma unroll
    for (int mi = 0; mi < 4; mi++)
#pragma unroll
        for (int rh = 0; rh < 2; rh++)
            zn[mi * 2 + rh] = g_znorm[(blockIdx.x << 7) + mbase + mi * 16 + rh * 8 + (lane >> 2)];

    float bv[8]; int bi[8];
#pragma unroll
    for (int r = 0; r < 8; r++) { bv[r] = 3.0e38f; bi[r] = 0; }

    // ldmatrix base addresses (conflict-free with 272B row stride)
    uint32_t a_base = SA + (uint32_t)(mbase + (lane & 15)) * RB2 + ((lane >> 4) & 1) * 16;
    uint32_t b_roff = (uint32_t)(nbw + (lane & 7)) * RB2 + ((lane >> 3) & 1) * 16;

    float acc[4][4][4];
    int ph0 = 0, ph1 = 0;

    for (int j = 0; j < 128; j++) {
        int cur = j & 1;
        uint32_t Bcur = cur ? SB1 : SB0;
        uint32_t bar  = cur ? MB1 : MB0;

        // wait for this buffer's bulk copy (iter 0 also covers A)
        if (cur) { mbar_wait(MB1, ph1 & 1); ph1++; }
        else     { mbar_wait(MB0, ph0 & 1); ph0++; }

        float en[8];
        load_en(j, nbw, lane, en);

        mma_phase(a_base, Bcur + b_roff, acc);
        epi_phase(acc, en, zn, j, nbw, lane, bv, bi);

        __syncthreads();   // all reads of Bcur complete before re-arm/overwrite

        // prefetch B(j+2) into this same buffer (one full iteration of cover)
        if (tid == 0 && j + 2 < 128) {
            mbar_expect_tx(bar, TILE2_BYTES);
            bulk_cp(Bcur, g_ef + (size_t)(j + 2) * 128 * RS2, TILE2_BYTES, bar);
        }
    }

    // quad reduce (cols within warp): lanes differing in (lane&3)
#pragma unroll
    for (int r = 0; r < 8; r++) {
#pragma unroll
        for (int off = 1; off <= 2; off <<= 1) {
            float ov = __shfl_xor_sync(0xffffffffu, bv[r], off);
            int   oi = __shfl_xor_sync(0xffffffffu, bi[r], off);
            if (ov < bv[r] || (ov == bv[r] && oi < bi[r])) { bv[r] = ov; bi[r] = oi; }
        }
    }
    __syncthreads();
    float* rv = (float*)(sm + TILE2_BYTES);          // reuse B0: 128 rows x 4 nwarps
    int*   ri = (int*)(sm + TILE2_BYTES + 2048);
    if ((lane & 3) == 0) {
#pragma unroll
        for (int r = 0; r < 8; r++) {
            int row = mbase + (r >> 1) * 16 + (r & 1) * 8 + (lane >> 2);
            rv[row * 4 + nw] = bv[r];
            ri[row * 4 + nw] = bi[r];
        }
    }
    __syncthreads();
    if (tid < 128) {
        float v = rv[tid * 4]; int ii = ri[tid * 4];
#pragma unroll
        for (int x = 1; x < 4; x++) {
            float ov = rv[tid * 4 + x]; int oi = ri[tid * 4 + x];
            if (ov < v || (ov == v && oi < ii)) { v = ov; ii = oi; }
        }
        int t = (blockIdx.x << 7) + tid;
        g_idx[t] = ii;
        out[1048579 + t] = (float)ii;
        atomicAdd(&g_counts[ii], 1);
    }
}

// ---------------- z_q gather + loss accumulation ----------------
__global__ void k_zq(const float* __restrict__ z, const float* __restrict__ emb,
                     float* __restrict__ out) {
    int p = blockIdx.x;            // 1024 planes = (b,c)
    int b = p >> 6, c = p & 63;
    int tid = threadIdx.x;         // 256
    float ls = 0.f;
    for (int hw = tid; hw < 1024; hw += 256) {
        int t = (b << 10) + hw;
        int id = g_idx[t];
        float v  = emb[(size_t)id * 64 + c];
        float zv = z[(size_t)p * 1024 + hw];
        out[(size_t)p * 1024 + hw] = v;
        float df = v - zv;
        ls += df * df;
    }
    __shared__ float red[8];
    for (int o = 16; o > 0; o >>= 1) ls += __shfl_down_sync(0xffffffff, ls, o);
    if ((tid & 31) == 0) red[tid >> 5] = ls;
    __syncthreads();
    if (tid == 0) {
        float s = 0.f;
        for (int w = 0; w < 8; w++) s += red[w];
        atomicAdd(&g_loss, s);
    }
}

// ---------------- entropy (parallel) + final scalar writes (ticket) ----------------
__global__ void k_ent(float* __restrict__ out) {
    int tid = threadIdx.x;                      // 1024, grid 16
    int n = blockIdx.x * 1024 + tid;
    int c = g_counts[n];
    float avg = (float)c * (1.0f / 16384.0f);
    float term = avg * logf(avg + 1e-10f);
    int cu = (c > 0) ? 1 : 0;
    for (int o = 16; o > 0; o >>= 1) {
        term += __shfl_down_sync(0xffffffffu, term, o);
        cu   += __shfl_down_sync(0xffffffffu, cu, o);
    }
    __shared__ float se[32]; __shared__ int sc[32];
    if ((tid & 31) == 0) { se[tid >> 5] = term; sc[tid >> 5] = cu; }
    __syncthreads();
    if (tid == 0) {
        float s = 0.f; int k = 0;
        for (int w = 0; w < 32; w++) { s += se[w]; k += sc[w]; }
        atomicAdd(&g_ent, s);
        atomicAdd(&g_cu, k);
        __threadfence();
        int tk = atomicAdd(&g_tick, 1);
        if (tk == 15) {
            out[1048576] = g_loss * (1.0f + BETA) / 1048576.0f;
            out[1048577] = expf(-g_ent);
            out[1048578] = (float)g_cu;
        }
    }
}

// ---------------- launch ----------------
extern "C" void kernel_launch(void* const* d_in, const int* in_sizes, int n_in,
                              void* d_out, int out_size) {
    const float* z   = (const float*)d_in[0];   // (16,64,32,32)
    const float* emb = (const float*)d_in[1];   // (16384,64)
    float* out = (float*)d_out;

    cudaFuncSetAttribute(k_split, cudaFuncAttributeMaxDynamicSharedMemorySize, TILE2_BYTES);
    cudaFuncSetAttribute(k_mma,   cudaFuncAttributeMaxDynamicSharedMemorySize, SM_TOT);

    k_split<<<256, 256, TILE2_BYTES>>>(z, emb);
    k_mma<<<128, 256, SM_TOT>>>(out);
    k_zq<<<1024, 256>>>(z, emb, out);
    k_ent<<<16, 1024>>>(out);
}